// round 3
// baseline (speedup 1.0000x reference)
#include <cuda_runtime.h>

// Fixed shapes for Latency_78632261255775:
//   x: [8, 3, 224, 224] fp32, T = 100
//   out: [8, 100, 3, 224, 224] fp32
#define N_ELEM   1204224        // 8*3*224*224
#define N4       301056         // N_ELEM/4
#define CHW      150528         // 3*224*224
#define CHW4     37632          // CHW/4
#define BATCH    8
#define T_STEPS  100
#define MM_BLOCKS 1184          // 8 blocks/SM, one wave

__device__ unsigned int g_min_bits;
__device__ unsigned int g_max_bits;
__device__ unsigned int g_part_min[MM_BLOCKS];
__device__ unsigned int g_part_max[MM_BLOCKS];
__device__ unsigned int g_count = 0;   // reset by last block each run (graph-replay safe)

// Order-preserving float <-> uint mapping (monotone for all finite floats).
__device__ __forceinline__ unsigned int f2u(float f) {
    unsigned int u = __float_as_uint(f);
    return (u & 0x80000000u) ? ~u : (u | 0x80000000u);
}
__device__ __forceinline__ float u2f(unsigned int u) {
    u = (u & 0x80000000u) ? (u & 0x7fffffffu) : ~u;
    return __uint_as_float(u);
}

__device__ __forceinline__ void block_reduce_minmax(unsigned int& lmin, unsigned int& lmax,
                                                    unsigned int* s_min, unsigned int* s_max) {
    #pragma unroll
    for (int off = 16; off > 0; off >>= 1) {
        lmin = min(lmin, __shfl_down_sync(0xFFFFFFFFu, lmin, off));
        lmax = max(lmax, __shfl_down_sync(0xFFFFFFFFu, lmax, off));
    }
    int wid = threadIdx.x >> 5;
    int lid = threadIdx.x & 31;
    if (lid == 0) { s_min[wid] = lmin; s_max[wid] = lmax; }
    __syncthreads();
    if (threadIdx.x < 32) {
        int nw = blockDim.x >> 5;
        lmin = (lid < nw) ? s_min[lid] : 0xFFFFFFFFu;
        lmax = (lid < nw) ? s_max[lid] : 0u;
        #pragma unroll
        for (int off = 4; off > 0; off >>= 1) {
            lmin = min(lmin, __shfl_down_sync(0xFFFFFFFFu, lmin, off));
            lmax = max(lmax, __shfl_down_sync(0xFFFFFFFFu, lmax, off));
        }
    }
}

__global__ void __launch_bounds__(256, 8) minmax_kernel(const float* __restrict__ x) {
    __shared__ unsigned int s_min[8], s_max[8];
    __shared__ bool s_last;
    unsigned int lmin = 0xFFFFFFFFu, lmax = 0u;
    int i = blockIdx.x * blockDim.x + threadIdx.x;   // one float4 per thread
    if (i < N4) {
        float4 v = ((const float4*)x)[i];
        unsigned int a = f2u(v.x), b = f2u(v.y), c = f2u(v.z), d = f2u(v.w);
        lmin = min(min(a, b), min(c, d));
        lmax = max(max(a, b), max(c, d));
    }
    block_reduce_minmax(lmin, lmax, s_min, s_max);
    if (threadIdx.x == 0) {
        g_part_min[blockIdx.x] = lmin;
        g_part_max[blockIdx.x] = lmax;
        __threadfence();
        unsigned int prev = atomicAdd(&g_count, 1u);
        s_last = (prev == gridDim.x - 1);
    }
    __syncthreads();
    if (s_last) {
        unsigned int fmin = 0xFFFFFFFFu, fmax = 0u;
        for (int i2 = threadIdx.x; i2 < MM_BLOCKS; i2 += blockDim.x) {
            fmin = min(fmin, g_part_min[i2]);
            fmax = max(fmax, g_part_max[i2]);
        }
        __syncthreads();   // reuse of s_min/s_max
        block_reduce_minmax(fmin, fmax, s_min, s_max);
        if (threadIdx.x == 0) {
            g_min_bits = fmin;
            g_max_bits = fmax;
            g_count = 0;               // reset for next graph replay
        }
    }
}

// Fused spike + one-hot fill.
// Each thread owns one uchar4-column (4 spatial elements) for ALL 100 time
// steps: compute the 4 spike indices once (exact reference FP sequence, IEEE
// ops, no fma/reciprocal), then emit 100 coalesced streaming float4 stores.
//   xn = (x - min) / ((max - min) + 1e-8)
//   st = clip(trunc((1 - xn) * 99), 0, 99)
__global__ void __launch_bounds__(256, 8) fill_kernel(const float* __restrict__ x,
                                                      float* __restrict__ out) {
    int chw4 = blockIdx.x * blockDim.x + threadIdx.x;  // 0 .. CHW4-1
    int b = blockIdx.y;
    float mn = u2f(g_min_bits);
    float mx = u2f(g_max_bits);
    float denom = __fadd_rn(__fsub_rn(mx, mn), 1e-8f);
    float4 v = ((const float4*)x)[b * CHW4 + chw4];    // L2-hit (read by minmax)
    int sx, sy, sz, sw;
    {
        float xn = __fdiv_rn(__fsub_rn(v.x, mn), denom);
        sx = max(0, min(99, (int)__fmul_rn(__fsub_rn(1.0f, xn), 99.0f)));
    }
    {
        float xn = __fdiv_rn(__fsub_rn(v.y, mn), denom);
        sy = max(0, min(99, (int)__fmul_rn(__fsub_rn(1.0f, xn), 99.0f)));
    }
    {
        float xn = __fdiv_rn(__fsub_rn(v.z, mn), denom);
        sz = max(0, min(99, (int)__fmul_rn(__fsub_rn(1.0f, xn), 99.0f)));
    }
    {
        float xn = __fdiv_rn(__fsub_rn(v.w, mn), denom);
        sw = max(0, min(99, (int)__fmul_rn(__fsub_rn(1.0f, xn), 99.0f)));
    }
    float4* base = (float4*)out + (size_t)b * T_STEPS * CHW4 + chw4;
    #pragma unroll 10
    for (int t = 0; t < T_STEPS; t++) {
        float4 o;
        o.x = (sx == t) ? 1.0f : 0.0f;
        o.y = (sy == t) ? 1.0f : 0.0f;
        o.z = (sz == t) ? 1.0f : 0.0f;
        o.w = (sw == t) ? 1.0f : 0.0f;
        __stcs(base + (size_t)t * CHW4, o);
    }
}

extern "C" void kernel_launch(void* const* d_in, const int* in_sizes, int n_in,
                              void* d_out, int out_size) {
    const float* x = (const float*)d_in[0];
    float* out = (float*)d_out;

    minmax_kernel<<<MM_BLOCKS, 256>>>(x);
    dim3 fgrid(CHW4 / 256, BATCH);        // (147, 8) — one wave of 1176 blocks
    fill_kernel<<<fgrid, 256>>>(x, out);
}

// round 4
// speedup vs baseline: 1.1005x; 1.1005x over previous
#include <cuda_runtime.h>

// Fixed shapes for Latency_78632261255775:
//   x: [8, 3, 224, 224] fp32, T = 100
//   out: [8, 100, 3, 224, 224] fp32
#define N_ELEM   1204224        // 8*3*224*224
#define N4       301056         // N_ELEM/4
#define CHW      150528         // 3*224*224
#define CHW4     37632          // CHW/4
#define BATCH    8
#define T_STEPS  100
#define T_PER    10             // time-steps per fill thread (R2 shape: best measured)
#define MM_BLOCKS 1176          // ceil(N4/256) = 1176, one wave

__device__ unsigned int g_min_bits;
__device__ unsigned int g_max_bits;
__device__ unsigned int g_part_min[MM_BLOCKS];
__device__ unsigned int g_part_max[MM_BLOCKS];
__device__ unsigned int g_count = 0;   // reset by last block each run (graph-replay safe)
__device__ unsigned char g_spikes[N_ELEM];

// Order-preserving float <-> uint mapping (monotone for all finite floats).
__device__ __forceinline__ unsigned int f2u(float f) {
    unsigned int u = __float_as_uint(f);
    return (u & 0x80000000u) ? ~u : (u | 0x80000000u);
}
__device__ __forceinline__ float u2f(unsigned int u) {
    u = (u & 0x80000000u) ? (u & 0x7fffffffu) : ~u;
    return __uint_as_float(u);
}

__device__ __forceinline__ void block_reduce_minmax(unsigned int& lmin, unsigned int& lmax,
                                                    unsigned int* s_min, unsigned int* s_max) {
    #pragma unroll
    for (int off = 16; off > 0; off >>= 1) {
        lmin = min(lmin, __shfl_down_sync(0xFFFFFFFFu, lmin, off));
        lmax = max(lmax, __shfl_down_sync(0xFFFFFFFFu, lmax, off));
    }
    int wid = threadIdx.x >> 5;
    int lid = threadIdx.x & 31;
    if (lid == 0) { s_min[wid] = lmin; s_max[wid] = lmax; }
    __syncthreads();
    if (threadIdx.x < 32) {
        int nw = blockDim.x >> 5;
        lmin = (lid < nw) ? s_min[lid] : 0xFFFFFFFFu;
        lmax = (lid < nw) ? s_max[lid] : 0u;
        #pragma unroll
        for (int off = 4; off > 0; off >>= 1) {
            lmin = min(lmin, __shfl_down_sync(0xFFFFFFFFu, lmin, off));
            lmax = max(lmax, __shfl_down_sync(0xFFFFFFFFu, lmax, off));
        }
    }
}

// One float4 per thread, single wave, last-block-done final reduce.
__global__ void __launch_bounds__(256, 8) minmax_kernel(const float* __restrict__ x) {
    __shared__ unsigned int s_min[8], s_max[8];
    __shared__ bool s_last;
    unsigned int lmin = 0xFFFFFFFFu, lmax = 0u;
    int i = blockIdx.x * blockDim.x + threadIdx.x;
    if (i < N4) {
        float4 v = ((const float4*)x)[i];
        unsigned int a = f2u(v.x), b = f2u(v.y), c = f2u(v.z), d = f2u(v.w);
        lmin = min(min(a, b), min(c, d));
        lmax = max(max(a, b), max(c, d));
    }
    block_reduce_minmax(lmin, lmax, s_min, s_max);
    if (threadIdx.x == 0) {
        g_part_min[blockIdx.x] = lmin;
        g_part_max[blockIdx.x] = lmax;
        __threadfence();
        unsigned int prev = atomicAdd(&g_count, 1u);
        s_last = (prev == gridDim.x - 1);
    }
    __syncthreads();
    if (s_last) {
        unsigned int fmin = 0xFFFFFFFFu, fmax = 0u;
        for (int i2 = threadIdx.x; i2 < MM_BLOCKS; i2 += blockDim.x) {
            fmin = min(fmin, g_part_min[i2]);
            fmax = max(fmax, g_part_max[i2]);
        }
        __syncthreads();   // s_min/s_max reuse
        block_reduce_minmax(fmin, fmax, s_min, s_max);
        if (threadIdx.x == 0) {
            g_min_bits = fmin;
            g_max_bits = fmax;
            g_count = 0;               // reset for next graph replay
        }
    }
}

// Per-element time-to-first-spike index as uint8.
// FP sequence must match the reference exactly (IEEE ops, no fma/reciprocal):
//   xn = (x - min) / ((max - min) + 1e-8)
//   st = clip(trunc((1 - xn) * 99), 0, 99)
__global__ void __launch_bounds__(256, 8) spike_kernel(const float* __restrict__ x) {
    int i = blockIdx.x * blockDim.x + threadIdx.x;   // 0 .. N4-1
    if (i >= N4) return;
    float mn = u2f(g_min_bits);
    float mx = u2f(g_max_bits);
    float denom = __fadd_rn(__fsub_rn(mx, mn), 1e-8f);
    float4 v = ((const float4*)x)[i];                // L2-hit (read by minmax)
    uchar4 st;
    {
        float xn = __fdiv_rn(__fsub_rn(v.x, mn), denom);
        int s = (int)__fmul_rn(__fsub_rn(1.0f, xn), 99.0f);
        st.x = (unsigned char)max(0, min(99, s));
    }
    {
        float xn = __fdiv_rn(__fsub_rn(v.y, mn), denom);
        int s = (int)__fmul_rn(__fsub_rn(1.0f, xn), 99.0f);
        st.y = (unsigned char)max(0, min(99, s));
    }
    {
        float xn = __fdiv_rn(__fsub_rn(v.z, mn), denom);
        int s = (int)__fmul_rn(__fsub_rn(1.0f, xn), 99.0f);
        st.z = (unsigned char)max(0, min(99, s));
    }
    {
        float xn = __fdiv_rn(__fsub_rn(v.w, mn), denom);
        int s = (int)__fmul_rn(__fsub_rn(1.0f, xn), 99.0f);
        st.w = (unsigned char)max(0, min(99, s));
    }
    ((uchar4*)g_spikes)[i] = st;
}

// One-hot fill: out[b, t, chw] = (spike[b, chw] == t).
// R2 shape (measured best): each thread owns one uchar4 of spikes and T_PER
// consecutive t values — 1 L2-hit spike load amortized over T_PER coalesced
// streaming float4 stores; 11760 blocks give multi-wave load balancing.
__global__ void __launch_bounds__(256, 8) fill_kernel(float* __restrict__ out) {
    int chw4 = blockIdx.x * blockDim.x + threadIdx.x;  // 0 .. CHW4-1
    int t0 = blockIdx.y * T_PER;
    int b = blockIdx.z;
    uchar4 st = ((const uchar4*)g_spikes)[b * CHW4 + chw4];
    int sx = st.x, sy = st.y, sz = st.z, sw = st.w;
    float4* base = (float4*)out + (size_t)(b * T_STEPS + t0) * CHW4 + chw4;
    #pragma unroll
    for (int k = 0; k < T_PER; k++) {
        int t = t0 + k;
        float4 o;
        o.x = (sx == t) ? 1.0f : 0.0f;
        o.y = (sy == t) ? 1.0f : 0.0f;
        o.z = (sz == t) ? 1.0f : 0.0f;
        o.w = (sw == t) ? 1.0f : 0.0f;
        __stcs(base + (size_t)k * CHW4, o);
    }
}

extern "C" void kernel_launch(void* const* d_in, const int* in_sizes, int n_in,
                              void* d_out, int out_size) {
    const float* x = (const float*)d_in[0];
    float* out = (float*)d_out;

    minmax_kernel<<<MM_BLOCKS, 256>>>(x);
    spike_kernel<<<MM_BLOCKS, 256>>>(x);
    dim3 fgrid(CHW4 / 256, T_STEPS / T_PER, BATCH);   // (147, 10, 8)
    fill_kernel<<<fgrid, 256>>>(out);
}